// round 4
// baseline (speedup 1.0000x reference)
#include <cuda_runtime.h>
#include <cuda_bf16.h>
#include <cstddef>

// ---------------- problem constants ----------------
#define NN 20000
#define EE 240000
#define GG 128
#define F_IN 128
#define EMB 256
#define HH 2
#define HC 512          // H*EMB
#define DENSE 512
#define NCLS 10

// ---------------- packed f32x2 helpers (sm_103a) ----------------
#define FMA_F32X2(d, a, b) \
    asm("fma.rn.f32x2 %0, %1, %2, %0;" : "+l"(d) : "l"(a), "l"(b))
#define UNPACK_F32X2(lo, hi, in) \
    asm("mov.b64 {%0, %1}, %2;" : "=f"(lo), "=f"(hi) : "l"(in))

// ---------------- scratch (device globals; no allocation) ----------------
#define OFF_H     0                         // [N,512]
#define OFF_GAT   (OFF_H   + NN*512)        // [N,512]
#define OFF_X     (OFF_GAT + NN*512)        // [N,256]
#define OFF_ALS   (OFF_X   + NN*256)        // [N,2]
#define OFF_ALD   (OFF_ALS + NN*2)          // [N,2]
#define OFF_POOL  (OFF_ALD + NN*2)          // [G,512] accumulated reps
#define OFF_DENSE (OFF_POOL + GG*512)       // [G,512]
#define FBUF_SZ   (OFF_DENSE + GG*512)

__device__ float g_fbuf[FBUF_SZ];

#define IOFF_DEG    0
#define IOFF_ROWS   (IOFF_DEG + NN)         // N+1
#define IOFF_WP     (IOFF_ROWS + NN + 1)    // N+1
#define IOFF_CSR    (IOFF_WP + NN + 1)      // E+N
#define IOFF_GSTART (IOFF_CSR + EE + NN)    // G+1
#define IBUF_SZ     (IOFF_GSTART + GG + 1)

__device__ int g_ibuf[IBUF_SZ];

// ---------------- init: deg=1 (self loop), zero pooled accumulator ----------------
__global__ void k_init(int* deg, float* pool) {
    int i = blockIdx.x * blockDim.x + threadIdx.x;
    if (i < NN) deg[i] = 1;
    if (i < GG * 512) pool[i] = 0.f;
}

// count in-degrees of real edges
__global__ void k_count(const int* __restrict__ ei, int* deg) {
    int e = blockIdx.x * blockDim.x + threadIdx.x;
    if (e < EE) atomicAdd(&deg[ei[EE + e]], 1);
}

// exclusive scan of deg[0..N) -> rows[0..N], single block of 1024
#define SCAN_T 1024
__global__ void k_scan(const int* __restrict__ deg, int* rows) {
    __shared__ int sh[SCAN_T];
    int tid = threadIdx.x;
    const int items = (NN + SCAN_T - 1) / SCAN_T;
    int start = tid * items;
    int local = 0;
    for (int i = 0; i < items; i++) {
        int idx = start + i;
        if (idx < NN) local += deg[idx];
    }
    sh[tid] = local;
    __syncthreads();
    for (int d = 1; d < SCAN_T; d <<= 1) {
        int v = (tid >= d) ? sh[tid - d] : 0;
        __syncthreads();
        sh[tid] += v;
        __syncthreads();
    }
    int run = sh[tid] - local;  // exclusive offset
    for (int i = 0; i < items; i++) {
        int idx = start + i;
        if (idx < NN) { rows[idx] = run; run += deg[idx]; }
    }
    if (tid == SCAN_T - 1) rows[NN] = sh[SCAN_T - 1];
}

__global__ void k_copy_wp(const int* __restrict__ rows, int* wp) {
    int i = blockIdx.x * blockDim.x + threadIdx.x;
    if (i <= NN) wp[i] = rows[i];
}

// scatter edges (and self loops) into CSR-by-dst
__global__ void k_scatter(const int* __restrict__ ei, int* wp, int* csr) {
    int i = blockIdx.x * blockDim.x + threadIdx.x;
    if (i >= EE + NN) return;
    int s, d;
    if (i < EE) { s = ei[i]; d = ei[EE + i]; }
    else        { s = d = i - EE; }
    int pos = atomicAdd(&wp[d], 1);
    csr[pos] = s;
}

// graph boundaries from sorted batch_index
__global__ void k_gstart(const int* __restrict__ batch, int* gstart) {
    int v = blockIdx.x * blockDim.x + threadIdx.x;
    if (v >= NN) return;
    int b = batch[v];
    if (v == 0) {
        for (int g = 0; g <= b; g++) gstart[g] = 0;
    } else {
        int bp = batch[v - 1];
        for (int g = bp + 1; g <= b; g++) gstart[g] = v;
    }
    if (v == NN - 1) {
        for (int g = b + 1; g <= GG; g++) gstart[g] = NN;
    }
}

// ---------------- tiled fp32 GEMM with packed f32x2 FMA --------------------
// C[M,Nc] = A[M,K]*B[K,Nc] (+bias)(+relu)
// Accumulators are packed pairs along M. B tile is stored duplicated ({b,b})
// and chunk-interleaved in shared so per-k reads are 6x LDS.128, conflict-free.
#define BM 128
#define BN 128
#define BK 8
__global__ __launch_bounds__(256, 3) void k_sgemm(
    const float* __restrict__ A, const float* __restrict__ B,
    const float* __restrict__ bias, float* __restrict__ C,
    int M, int K, int Nc, int doRelu)
{
    __shared__ float As[BK][BM];          // 4 KB
    __shared__ float BsD[BK][2 * BN];     // 8 KB, duplicated+interleaved
    int tid = threadIdx.x;
    int ty = tid / 16, tx = tid % 16;     // ty 0..15 rows-of-8, tx 0..15 cols-of-8
    int rowBase = blockIdx.y * BM;
    int colBase = blockIdx.x * BN;

    unsigned long long acc2[4][8];
#pragma unroll
    for (int ip = 0; ip < 4; ip++)
#pragma unroll
        for (int jj = 0; jj < 8; jj++) acc2[ip][jj] = 0ULL;

    int ar = tid >> 1;          // 0..127
    int ak = (tid & 1) * 4;     // 0 or 4
    int bk = tid >> 5;          // 0..7
    int bn = (tid & 31) * 4;    // 0..124

    for (int k0 = 0; k0 < K; k0 += BK) {
        // A tile -> As[k][m]
        float4 a4;
        int grow = rowBase + ar;
        if (grow < M) a4 = *(const float4*)(A + (size_t)grow * K + k0 + ak);
        else a4 = make_float4(0.f, 0.f, 0.f, 0.f);
        As[ak + 0][ar] = a4.x; As[ak + 1][ar] = a4.y;
        As[ak + 2][ar] = a4.z; As[ak + 3][ar] = a4.w;

        // B tile -> duplicated pairs, chunk-interleaved:
        // logical dup position p=2j{,+1}; chunk g=p/4; stored at float offset
        // (g%4)*64 + (g/4)*4  so 16 threads' chunk-c reads are contiguous.
        float4 b4 = *(const float4*)(B + (size_t)(k0 + bk) * Nc + colBase + bn);
        int g0 = bn >> 1;               // even
        int c0 = g0 & 3, t0 = g0 >> 2;
        *(float4*)&BsD[bk][c0 * 64 + t0 * 4] = make_float4(b4.x, b4.x, b4.y, b4.y);
        int g1 = g0 + 1;                // odd
        int c1 = g1 & 3, t1 = g1 >> 2;
        *(float4*)&BsD[bk][c1 * 64 + t1 * 4] = make_float4(b4.z, b4.z, b4.w, b4.w);
        __syncthreads();

#pragma unroll
        for (int k = 0; k < BK; k++) {
            // a-pairs: {A[2ip], A[2ip+1]} along M, direct 64-bit lanes
            ulonglong2 aA = *(const ulonglong2*)&As[k][ty * 8];
            ulonglong2 aB = *(const ulonglong2*)&As[k][ty * 8 + 4];
            unsigned long long a2[4] = {aA.x, aA.y, aB.x, aB.y};
            // b broadcast-pairs {b,b}: 4 conflict-free LDS.128
            unsigned long long b2[8];
#pragma unroll
            for (int c = 0; c < 4; c++) {
                ulonglong2 bb = *(const ulonglong2*)&BsD[k][c * 64 + tx * 4];
                b2[2 * c] = bb.x; b2[2 * c + 1] = bb.y;
            }
#pragma unroll
            for (int ip = 0; ip < 4; ip++)
#pragma unroll
                for (int jj = 0; jj < 8; jj++)
                    FMA_F32X2(acc2[ip][jj], a2[ip], b2[jj]);
        }
        __syncthreads();
    }

    // epilogue: unpack pairs (lo=row 2ip, hi=row 2ip+1), bias+relu, store
#pragma unroll
    for (int ip = 0; ip < 4; ip++) {
        float lo[8], hi[8];
#pragma unroll
        for (int jj = 0; jj < 8; jj++)
            UNPACK_F32X2(lo[jj], hi[jj], acc2[ip][jj]);
        int r0 = rowBase + ty * 8 + 2 * ip;
        int cbase = colBase + tx * 8;
#pragma unroll
        for (int half = 0; half < 2; half++) {
            int r = r0 + half;
            if (r >= M) continue;
            float* src = half ? hi : lo;
#pragma unroll
            for (int j4 = 0; j4 < 8; j4 += 4) {
                int cidx = cbase + j4;
                float4 v = make_float4(src[j4], src[j4 + 1], src[j4 + 2], src[j4 + 3]);
                if (bias) {
                    v.x += bias[cidx]; v.y += bias[cidx + 1];
                    v.z += bias[cidx + 2]; v.w += bias[cidx + 3];
                }
                if (doRelu) {
                    v.x = fmaxf(v.x, 0.f); v.y = fmaxf(v.y, 0.f);
                    v.z = fmaxf(v.z, 0.f); v.w = fmaxf(v.w, 0.f);
                }
                *(float4*)(C + (size_t)r * Nc + cidx) = v;
            }
        }
    }
}

// ---------------- per-node attention logit terms ----------------
__global__ void k_al(const float* __restrict__ h, const float* __restrict__ asrc,
                     const float* __restrict__ adst, float* __restrict__ als,
                     float* __restrict__ ald)
{
    int warp = (blockIdx.x * blockDim.x + threadIdx.x) >> 5;
    int lane = threadIdx.x & 31;
    if (warp >= NN) return;
    const float* hr = h + (size_t)warp * 512;
    float s0 = 0.f, s1 = 0.f, d0 = 0.f, d1 = 0.f;
#pragma unroll
    for (int i = 0; i < 8; i++) {
        int c = i * 32 + lane;
        float h0 = hr[c], h1 = hr[256 + c];
        s0 += h0 * asrc[c];        d0 += h0 * adst[c];
        s1 += h1 * asrc[256 + c];  d1 += h1 * adst[256 + c];
    }
#pragma unroll
    for (int off = 16; off; off >>= 1) {
        s0 += __shfl_xor_sync(0xffffffffu, s0, off);
        s1 += __shfl_xor_sync(0xffffffffu, s1, off);
        d0 += __shfl_xor_sync(0xffffffffu, d0, off);
        d1 += __shfl_xor_sync(0xffffffffu, d1, off);
    }
    if (lane == 0) {
        als[warp * 2] = s0; als[warp * 2 + 1] = s1;
        ald[warp * 2] = d0; ald[warp * 2 + 1] = d1;
    }
}

// ---------------- attention softmax + aggregation (one warp per dst node) -----------
__global__ void k_attn(const float* __restrict__ h, const float* __restrict__ als,
                       const float* __restrict__ ald, const float* __restrict__ bvec,
                       const int* __restrict__ rows, const int* __restrict__ csr,
                       float* __restrict__ out)
{
    int warp = (blockIdx.x * blockDim.x + threadIdx.x) >> 5;
    int lane = threadIdx.x & 31;
    if (warp >= NN) return;
    int v = warp;
    int s0 = rows[v], s1 = rows[v + 1];
    int deg = s1 - s0;
    float ad0 = ald[v * 2], ad1 = ald[v * 2 + 1];

    // pass 1: max logit per head
    float m0 = -1e30f, m1 = -1e30f;
    for (int base = 0; base < deg; base += 32) {
        int j = base + lane;
        if (j < deg) {
            int s = csr[s0 + j];
            float t0 = als[s * 2] + ad0;     t0 = fmaxf(t0, 0.2f * t0);
            float t1 = als[s * 2 + 1] + ad1; t1 = fmaxf(t1, 0.2f * t1);
            m0 = fmaxf(m0, t0); m1 = fmaxf(m1, t1);
        }
    }
#pragma unroll
    for (int off = 16; off; off >>= 1) {
        m0 = fmaxf(m0, __shfl_xor_sync(0xffffffffu, m0, off));
        m1 = fmaxf(m1, __shfl_xor_sync(0xffffffffu, m1, off));
    }

    // pass 2: exp weights + weighted aggregation, 2 edges/iter for load MLP
    float acc[16];
#pragma unroll
    for (int k = 0; k < 16; k++) acc[k] = 0.f;
    float den0 = 0.f, den1 = 0.f;
    int j = 0;
    for (; j + 2 <= deg; j += 2) {
        int sa = csr[s0 + j];
        int sb = csr[s0 + j + 1];
        float ta0 = als[sa * 2] + ad0;     ta0 = fmaxf(ta0, 0.2f * ta0);
        float ta1 = als[sa * 2 + 1] + ad1; ta1 = fmaxf(ta1, 0.2f * ta1);
        float tb0 = als[sb * 2] + ad0;     tb0 = fmaxf(tb0, 0.2f * tb0);
        float tb1 = als[sb * 2 + 1] + ad1; tb1 = fmaxf(tb1, 0.2f * tb1);
        float wa0 = __expf(ta0 - m0), wa1 = __expf(ta1 - m1);
        float wb0 = __expf(tb0 - m0), wb1 = __expf(tb1 - m1);
        den0 += wa0 + wb0; den1 += wa1 + wb1;
        const float* ha = h + (size_t)sa * 512 + lane;
        const float* hb = h + (size_t)sb * 512 + lane;
#pragma unroll
        for (int k = 0; k < 16; k++) {
            float va = ha[k * 32];
            float vb = hb[k * 32];
            acc[k] += (k < 8 ? wa0 : wa1) * va + (k < 8 ? wb0 : wb1) * vb;
        }
    }
    for (; j < deg; j++) {
        int s = csr[s0 + j];
        float t0 = als[s * 2] + ad0;     t0 = fmaxf(t0, 0.2f * t0);
        float t1 = als[s * 2 + 1] + ad1; t1 = fmaxf(t1, 0.2f * t1);
        float w0 = __expf(t0 - m0), w1 = __expf(t1 - m1);
        den0 += w0; den1 += w1;
        const float* hr = h + (size_t)s * 512 + lane;
#pragma unroll
        for (int k = 0; k < 16; k++)
            acc[k] += (k < 8 ? w0 : w1) * hr[k * 32];
    }
    float r0 = 1.0f / den0, r1 = 1.0f / den1;
    float* orow = out + (size_t)v * 512 + lane;
#pragma unroll
    for (int k = 0; k < 16; k++) {
        float val = acc[k] * (k < 8 ? r0 : r1) + bvec[k * 32 + lane];
        orow[k * 32] = fmaxf(val, 0.f);   // fused relu (post-GAT)
    }
}

// ---------------- pooling: per-graph max + mean, accumulated across layers ----------
__global__ void k_pool(const float* __restrict__ x, const int* __restrict__ gstart,
                       float* __restrict__ gacc)
{
    int g = blockIdx.x;
    int c = threadIdx.x;   // 256
    int s = gstart[g], e = gstart[g + 1];
    float mx = 0.f, sm = 0.f;   // post-relu values are >= 0
    int v = s;
    for (; v + 2 <= e; v += 2) {
        float a = x[(size_t)v * 256 + c];
        float b = x[(size_t)(v + 1) * 256 + c];
        sm += a + b; mx = fmaxf(mx, fmaxf(a, b));
    }
    if (v < e) {
        float a = x[(size_t)v * 256 + c];
        sm += a; mx = fmaxf(mx, a);
    }
    int cnt = e - s;
    float mean = (cnt > 0) ? sm / (float)cnt : 0.f;
    gacc[g * 512 + c]       += mx;
    gacc[g * 512 + 256 + c] += mean;
}

// ---------------- final tiny linear: [G,512] @ [512,10] + b ----------------
__global__ void k_line2(const float* __restrict__ gd, const float* __restrict__ W,
                        const float* __restrict__ b, float* __restrict__ out)
{
    __shared__ float sh[512];
    int g = blockIdx.x;
    for (int i = threadIdx.x; i < 512; i += blockDim.x) sh[i] = gd[g * 512 + i];
    __syncthreads();
    if (threadIdx.x < NCLS) {
        float acc = b[threadIdx.x];
        for (int k = 0; k < 512; k++) acc += sh[k] * W[k * NCLS + threadIdx.x];
        out[g * NCLS + threadIdx.x] = acc;
    }
}

// ---------------- host orchestration ----------------
extern "C" void kernel_launch(void* const* d_in, const int* in_sizes, int n_in,
                              void* d_out, int out_size)
{
    const float* x_in  = (const float*)d_in[0];
    const int*   ei    = (const int*)d_in[1];
    const int*   batch = (const int*)d_in[2];
    const float* attW[3]  = {(const float*)d_in[3],  (const float*)d_in[9],  (const float*)d_in[15]};
    const float* asrc[3]  = {(const float*)d_in[4],  (const float*)d_in[10], (const float*)d_in[16]};
    const float* adst[3]  = {(const float*)d_in[5],  (const float*)d_in[11], (const float*)d_in[17]};
    const float* attb[3]  = {(const float*)d_in[6],  (const float*)d_in[12], (const float*)d_in[18]};
    const float* linW[3]  = {(const float*)d_in[7],  (const float*)d_in[13], (const float*)d_in[19]};
    const float* linb[3]  = {(const float*)d_in[8],  (const float*)d_in[14], (const float*)d_in[20]};
    const float* line1W = (const float*)d_in[21];
    const float* line1b = (const float*)d_in[22];
    const float* line2W = (const float*)d_in[23];
    const float* line2b = (const float*)d_in[24];
    float* out = (float*)d_out;

    static float* fbuf = nullptr;
    static int*   ibuf = nullptr;
    if (!fbuf) {
        cudaGetSymbolAddress((void**)&fbuf, g_fbuf);
        cudaGetSymbolAddress((void**)&ibuf, g_ibuf);
    }

    float* bh    = fbuf + OFF_H;
    float* bgat  = fbuf + OFF_GAT;
    float* bx    = fbuf + OFF_X;
    float* bals  = fbuf + OFF_ALS;
    float* bald  = fbuf + OFF_ALD;
    float* bpool = fbuf + OFF_POOL;
    float* bdense= fbuf + OFF_DENSE;
    int* deg    = ibuf + IOFF_DEG;
    int* rows   = ibuf + IOFF_ROWS;
    int* wp     = ibuf + IOFF_WP;
    int* csr    = ibuf + IOFF_CSR;
    int* gstart = ibuf + IOFF_GSTART;

    // ---- graph preprocessing (every call; deterministic work) ----
    {
        int n = GG * 512;  // >= NN
        k_init<<<(n + 255) / 256, 256>>>(deg, bpool);
        k_count<<<(EE + 255) / 256, 256>>>(ei, deg);
        k_scan<<<1, SCAN_T>>>(deg, rows);
        k_copy_wp<<<(NN + 256) / 256, 256>>>(rows, wp);
        k_scatter<<<(EE + NN + 255) / 256, 256>>>(ei, wp, csr);
        k_gstart<<<(NN + 255) / 256, 256>>>(batch, gstart);
    }

    // ---- three GAT layers ----
    const float* xcur = x_in;
    int fin = F_IN;
    for (int i = 0; i < 3; i++) {
        // h = x @ W   [N,fin] x [fin,512]
        {
            dim3 grid(HC / BN, (NN + BM - 1) / BM);
            k_sgemm<<<grid, 256>>>(xcur, attW[i], nullptr, bh, NN, fin, HC, 0);
        }
        // per-node attention terms
        k_al<<<(NN * 32 + 255) / 256, 256>>>(bh, asrc[i], adst[i], bals, bald);
        // softmax-attention aggregation (+ bias + relu)
        k_attn<<<(NN * 32 + 255) / 256, 256>>>(bh, bals, bald, attb[i], rows, csr, bgat);
        // x = relu(gat @ lin_W + lin_b)   [N,512] x [512,256]
        {
            dim3 grid(EMB / BN, (NN + BM - 1) / BM);
            k_sgemm<<<grid, 256>>>(bgat, linW[i], linb[i], bx, NN, HC, EMB, 1);
        }
        // pooling accumulation
        k_pool<<<GG, 256>>>(bx, gstart, bpool);
        xcur = bx;
        fin = EMB;
    }

    // ---- MLP head ----
    {
        dim3 grid(DENSE / BN, (GG + BM - 1) / BM);
        k_sgemm<<<grid, 256>>>(bpool, line1W, line1b, bdense, GG, 2 * EMB, DENSE, 1);
    }
    k_line2<<<GG, 512>>>(bdense, line2W, line2b, out);
}

// round 5
// speedup vs baseline: 1.9252x; 1.9252x over previous
#include <cuda_runtime.h>
#include <cuda_bf16.h>
#include <cstddef>

// ---------------- problem constants ----------------
#define NN 20000
#define EE 240000
#define GG 128
#define F_IN 128
#define EMB 256
#define HH 2
#define HC 512          // H*EMB
#define DENSE 512
#define NCLS 10

// ---------------- packed f32x2 helpers (sm_103a) ----------------
#define FMA_F32X2(d, a, b) \
    asm("fma.rn.f32x2 %0, %1, %2, %0;" : "+l"(d) : "l"(a), "l"(b))
#define UNPACK_F32X2(lo, hi, in) \
    asm("mov.b64 {%0, %1}, %2;" : "=f"(lo), "=f"(hi) : "l"(in))

// ---------------- scratch (device globals; no allocation) ----------------
#define OFF_H     0                         // [N,512]
#define OFF_GAT   (OFF_H   + NN*512)        // [N,512]
#define OFF_X     (OFF_GAT + NN*512)        // [N,256]
#define OFF_ALS   (OFF_X   + NN*256)        // [N,2]
#define OFF_ALD   (OFF_ALS + NN*2)          // [N,2]
#define OFF_POOL  (OFF_ALD + NN*2)          // [G,512] accumulated reps
#define OFF_DENSE (OFF_POOL + GG*512)       // [G,512]
#define FBUF_SZ   (OFF_DENSE + GG*512)

__device__ float g_fbuf[FBUF_SZ];

#define IOFF_DEG    0
#define IOFF_ROWS   (IOFF_DEG + NN)         // N+1
#define IOFF_WP     (IOFF_ROWS + NN + 1)    // N+1
#define IOFF_CSR    (IOFF_WP + NN + 1)      // E+N
#define IOFF_GSTART (IOFF_CSR + EE + NN)    // G+1
#define IBUF_SZ     (IOFF_GSTART + GG + 1)

__device__ int g_ibuf[IBUF_SZ];

// ---------------- init: deg=1 (self loop), zero pooled accumulator ----------------
__global__ void k_init(int* deg, float* pool) {
    int i = blockIdx.x * blockDim.x + threadIdx.x;
    if (i < NN) deg[i] = 1;
    if (i < GG * 512) pool[i] = 0.f;
}

// count in-degrees of real edges
__global__ void k_count(const int* __restrict__ ei, int* deg) {
    int e = blockIdx.x * blockDim.x + threadIdx.x;
    if (e < EE) atomicAdd(&deg[ei[EE + e]], 1);
}

// exclusive scan of deg[0..N) -> rows[0..N] AND wp[0..N], single block of 1024
#define SCAN_T 1024
__global__ void k_scan(const int* __restrict__ deg, int* rows, int* wp) {
    __shared__ int sh[SCAN_T];
    int tid = threadIdx.x;
    const int items = (NN + SCAN_T - 1) / SCAN_T;
    int start = tid * items;
    int local = 0;
    for (int i = 0; i < items; i++) {
        int idx = start + i;
        if (idx < NN) local += deg[idx];
    }
    sh[tid] = local;
    __syncthreads();
    for (int d = 1; d < SCAN_T; d <<= 1) {
        int v = (tid >= d) ? sh[tid - d] : 0;
        __syncthreads();
        sh[tid] += v;
        __syncthreads();
    }
    int run = sh[tid] - local;  // exclusive offset
    for (int i = 0; i < items; i++) {
        int idx = start + i;
        if (idx < NN) { rows[idx] = run; wp[idx] = run; run += deg[idx]; }
    }
    if (tid == SCAN_T - 1) { rows[NN] = sh[SCAN_T - 1]; wp[NN] = sh[SCAN_T - 1]; }
}

// scatter edges (and self loops) into CSR-by-dst
__global__ void k_scatter(const int* __restrict__ ei, int* wp, int* csr) {
    int i = blockIdx.x * blockDim.x + threadIdx.x;
    if (i >= EE + NN) return;
    int s, d;
    if (i < EE) { s = ei[i]; d = ei[EE + i]; }
    else        { s = d = i - EE; }
    int pos = atomicAdd(&wp[d], 1);
    csr[pos] = s;
}

// graph boundaries from sorted batch_index
__global__ void k_gstart(const int* __restrict__ batch, int* gstart) {
    int v = blockIdx.x * blockDim.x + threadIdx.x;
    if (v >= NN) return;
    int b = batch[v];
    if (v == 0) {
        for (int g = 0; g <= b; g++) gstart[g] = 0;
    } else {
        int bp = batch[v - 1];
        for (int g = bp + 1; g <= b; g++) gstart[g] = v;
    }
    if (v == NN - 1) {
        for (int g = b + 1; g <= GG; g++) gstart[g] = NN;
    }
}

// ---------------- tiled fp32 GEMM with packed f32x2 FMA --------------------
// C[M,Nc] = A[M,K]*B[K,Nc] (+bias)(+relu)
// Accumulators are packed pairs along M. B tile is stored duplicated ({b,b})
// and chunk-interleaved in shared so per-k reads are 6x LDS.128, conflict-free.
// launch_bounds(256,2): 128-reg cap -> NO spill (kernel needs ~110 regs).
#define BM 128
#define BN 128
#define BK 8
__global__ __launch_bounds__(256, 2) void k_sgemm(
    const float* __restrict__ A, const float* __restrict__ B,
    const float* __restrict__ bias, float* __restrict__ C,
    int M, int K, int Nc, int doRelu)
{
    __shared__ float As[BK][BM];          // 4 KB
    __shared__ float BsD[BK][2 * BN];     // 8 KB, duplicated+interleaved
    int tid = threadIdx.x;
    int ty = tid / 16, tx = tid % 16;     // ty 0..15 rows-of-8, tx 0..15 cols-of-8
    int rowBase = blockIdx.y * BM;
    int colBase = blockIdx.x * BN;

    unsigned long long acc2[4][8];
#pragma unroll
    for (int ip = 0; ip < 4; ip++)
#pragma unroll
        for (int jj = 0; jj < 8; jj++) acc2[ip][jj] = 0ULL;

    int ar = tid >> 1;          // 0..127
    int ak = (tid & 1) * 4;     // 0 or 4
    int bk = tid >> 5;          // 0..7
    int bn = (tid & 31) * 4;    // 0..124

    for (int k0 = 0; k0 < K; k0 += BK) {
        // A tile -> As[k][m]
        float4 a4;
        int grow = rowBase + ar;
        if (grow < M) a4 = *(const float4*)(A + (size_t)grow * K + k0 + ak);
        else a4 = make_float4(0.f, 0.f, 0.f, 0.f);
        As[ak + 0][ar] = a4.x; As[ak + 1][ar] = a4.y;
        As[ak + 2][ar] = a4.z; As[ak + 3][ar] = a4.w;

        // B tile -> duplicated pairs, chunk-interleaved:
        // logical dup position p=2j{,+1}; chunk g=p/4; stored at float offset
        // (g%4)*64 + (g/4)*4  so 16 threads' chunk-c reads are contiguous.
        float4 b4 = *(const float4*)(B + (size_t)(k0 + bk) * Nc + colBase + bn);
        int g0 = bn >> 1;               // even
        int c0 = g0 & 3, t0 = g0 >> 2;
        *(float4*)&BsD[bk][c0 * 64 + t0 * 4] = make_float4(b4.x, b4.x, b4.y, b4.y);
        int g1 = g0 + 1;                // odd
        int c1 = g1 & 3, t1 = g1 >> 2;
        *(float4*)&BsD[bk][c1 * 64 + t1 * 4] = make_float4(b4.z, b4.z, b4.w, b4.w);
        __syncthreads();

#pragma unroll
        for (int k = 0; k < BK; k++) {
            // a-pairs: {A[2ip], A[2ip+1]} along M, direct 64-bit lanes
            ulonglong2 aA = *(const ulonglong2*)&As[k][ty * 8];
            ulonglong2 aB = *(const ulonglong2*)&As[k][ty * 8 + 4];
            unsigned long long a2[4] = {aA.x, aA.y, aB.x, aB.y};
            // b broadcast-pairs {b,b}: 4 conflict-free LDS.128
            unsigned long long b2[8];
#pragma unroll
            for (int c = 0; c < 4; c++) {
                ulonglong2 bb = *(const ulonglong2*)&BsD[k][c * 64 + tx * 4];
                b2[2 * c] = bb.x; b2[2 * c + 1] = bb.y;
            }
#pragma unroll
            for (int ip = 0; ip < 4; ip++)
#pragma unroll
                for (int jj = 0; jj < 8; jj++)
                    FMA_F32X2(acc2[ip][jj], a2[ip], b2[jj]);
        }
        __syncthreads();
    }

    // epilogue: unpack pairs (lo=row 2ip, hi=row 2ip+1), bias+relu, store
#pragma unroll
    for (int ip = 0; ip < 4; ip++) {
        float lo[8], hi[8];
#pragma unroll
        for (int jj = 0; jj < 8; jj++)
            UNPACK_F32X2(lo[jj], hi[jj], acc2[ip][jj]);
        int r0 = rowBase + ty * 8 + 2 * ip;
        int cbase = colBase + tx * 8;
#pragma unroll
        for (int half = 0; half < 2; half++) {
            int r = r0 + half;
            if (r >= M) continue;
            float* src = half ? hi : lo;
#pragma unroll
            for (int j4 = 0; j4 < 8; j4 += 4) {
                int cidx = cbase + j4;
                float4 v = make_float4(src[j4], src[j4 + 1], src[j4 + 2], src[j4 + 3]);
                if (bias) {
                    v.x += bias[cidx]; v.y += bias[cidx + 1];
                    v.z += bias[cidx + 2]; v.w += bias[cidx + 3];
                }
                if (doRelu) {
                    v.x = fmaxf(v.x, 0.f); v.y = fmaxf(v.y, 0.f);
                    v.z = fmaxf(v.z, 0.f); v.w = fmaxf(v.w, 0.f);
                }
                *(float4*)(C + (size_t)r * Nc + cidx) = v;
            }
        }
    }
}

// ---------------- per-node attention logit terms ----------------
__global__ void k_al(const float* __restrict__ h, const float* __restrict__ asrc,
                     const float* __restrict__ adst, float* __restrict__ als,
                     float* __restrict__ ald)
{
    int warp = (blockIdx.x * blockDim.x + threadIdx.x) >> 5;
    int lane = threadIdx.x & 31;
    if (warp >= NN) return;
    const float* hr = h + (size_t)warp * 512;
    float s0 = 0.f, s1 = 0.f, d0 = 0.f, d1 = 0.f;
#pragma unroll
    for (int i = 0; i < 8; i++) {
        int c = i * 32 + lane;
        float h0 = hr[c], h1 = hr[256 + c];
        s0 += h0 * asrc[c];        d0 += h0 * adst[c];
        s1 += h1 * asrc[256 + c];  d1 += h1 * adst[256 + c];
    }
#pragma unroll
    for (int off = 16; off; off >>= 1) {
        s0 += __shfl_xor_sync(0xffffffffu, s0, off);
        s1 += __shfl_xor_sync(0xffffffffu, s1, off);
        d0 += __shfl_xor_sync(0xffffffffu, d0, off);
        d1 += __shfl_xor_sync(0xffffffffu, d1, off);
    }
    if (lane == 0) {
        als[warp * 2] = s0; als[warp * 2 + 1] = s1;
        ald[warp * 2] = d0; ald[warp * 2 + 1] = d1;
    }
}

// ---------------- attention softmax + aggregation (one warp per dst node) -----------
__global__ void k_attn(const float* __restrict__ h, const float* __restrict__ als,
                       const float* __restrict__ ald, const float* __restrict__ bvec,
                       const int* __restrict__ rows, const int* __restrict__ csr,
                       float* __restrict__ out)
{
    int warp = (blockIdx.x * blockDim.x + threadIdx.x) >> 5;
    int lane = threadIdx.x & 31;
    if (warp >= NN) return;
    int v = warp;
    int s0 = rows[v], s1 = rows[v + 1];
    int deg = s1 - s0;
    float ad0 = ald[v * 2], ad1 = ald[v * 2 + 1];

    // pass 1: max logit per head
    float m0 = -1e30f, m1 = -1e30f;
    for (int base = 0; base < deg; base += 32) {
        int j = base + lane;
        if (j < deg) {
            int s = csr[s0 + j];
            float t0 = als[s * 2] + ad0;     t0 = fmaxf(t0, 0.2f * t0);
            float t1 = als[s * 2 + 1] + ad1; t1 = fmaxf(t1, 0.2f * t1);
            m0 = fmaxf(m0, t0); m1 = fmaxf(m1, t1);
        }
    }
#pragma unroll
    for (int off = 16; off; off >>= 1) {
        m0 = fmaxf(m0, __shfl_xor_sync(0xffffffffu, m0, off));
        m1 = fmaxf(m1, __shfl_xor_sync(0xffffffffu, m1, off));
    }

    // pass 2: exp weights + weighted aggregation, 2 edges/iter for load MLP
    float acc[16];
#pragma unroll
    for (int k = 0; k < 16; k++) acc[k] = 0.f;
    float den0 = 0.f, den1 = 0.f;
    int j = 0;
    for (; j + 2 <= deg; j += 2) {
        int sa = csr[s0 + j];
        int sb = csr[s0 + j + 1];
        float ta0 = als[sa * 2] + ad0;     ta0 = fmaxf(ta0, 0.2f * ta0);
        float ta1 = als[sa * 2 + 1] + ad1; ta1 = fmaxf(ta1, 0.2f * ta1);
        float tb0 = als[sb * 2] + ad0;     tb0 = fmaxf(tb0, 0.2f * tb0);
        float tb1 = als[sb * 2 + 1] + ad1; tb1 = fmaxf(tb1, 0.2f * tb1);
        float wa0 = __expf(ta0 - m0), wa1 = __expf(ta1 - m1);
        float wb0 = __expf(tb0 - m0), wb1 = __expf(tb1 - m1);
        den0 += wa0 + wb0; den1 += wa1 + wb1;
        const float* ha = h + (size_t)sa * 512 + lane;
        const float* hb = h + (size_t)sb * 512 + lane;
#pragma unroll
        for (int k = 0; k < 16; k++) {
            float va = ha[k * 32];
            float vb = hb[k * 32];
            acc[k] += (k < 8 ? wa0 : wa1) * va + (k < 8 ? wb0 : wb1) * vb;
        }
    }
    for (; j < deg; j++) {
        int s = csr[s0 + j];
        float t0 = als[s * 2] + ad0;     t0 = fmaxf(t0, 0.2f * t0);
        float t1 = als[s * 2 + 1] + ad1; t1 = fmaxf(t1, 0.2f * t1);
        float w0 = __expf(t0 - m0), w1 = __expf(t1 - m1);
        den0 += w0; den1 += w1;
        const float* hr = h + (size_t)s * 512 + lane;
#pragma unroll
        for (int k = 0; k < 16; k++)
            acc[k] += (k < 8 ? w0 : w1) * hr[k * 32];
    }
    float r0 = 1.0f / den0, r1 = 1.0f / den1;
    float* orow = out + (size_t)v * 512 + lane;
#pragma unroll
    for (int k = 0; k < 16; k++) {
        float val = acc[k] * (k < 8 ? r0 : r1) + bvec[k * 32 + lane];
        orow[k * 32] = fmaxf(val, 0.f);   // fused relu (post-GAT)
    }
}

// ---------------- pooling: per-graph max + mean, accumulated across layers ----------
__global__ void k_pool(const float* __restrict__ x, const int* __restrict__ gstart,
                       float* __restrict__ gacc)
{
    int g = blockIdx.x;
    int c = threadIdx.x;   // 256
    int s = gstart[g], e = gstart[g + 1];
    float mx = 0.f, sm = 0.f;   // post-relu values are >= 0
    int v = s;
    for (; v + 2 <= e; v += 2) {
        float a = x[(size_t)v * 256 + c];
        float b = x[(size_t)(v + 1) * 256 + c];
        sm += a + b; mx = fmaxf(mx, fmaxf(a, b));
    }
    if (v < e) {
        float a = x[(size_t)v * 256 + c];
        sm += a; mx = fmaxf(mx, a);
    }
    int cnt = e - s;
    float mean = (cnt > 0) ? sm / (float)cnt : 0.f;
    gacc[g * 512 + c]       += mx;
    gacc[g * 512 + 256 + c] += mean;
}

// ---------------- final tiny linear: [G,512] @ [512,10] + b ----------------
__global__ void k_line2(const float* __restrict__ gd, const float* __restrict__ W,
                        const float* __restrict__ b, float* __restrict__ out)
{
    __shared__ float sh[512];
    int g = blockIdx.x;
    for (int i = threadIdx.x; i < 512; i += blockDim.x) sh[i] = gd[g * 512 + i];
    __syncthreads();
    if (threadIdx.x < NCLS) {
        float acc = b[threadIdx.x];
        for (int k = 0; k < 512; k++) acc += sh[k] * W[k * NCLS + threadIdx.x];
        out[g * NCLS + threadIdx.x] = acc;
    }
}

// ---------------- host orchestration ----------------
extern "C" void kernel_launch(void* const* d_in, const int* in_sizes, int n_in,
                              void* d_out, int out_size)
{
    const float* x_in  = (const float*)d_in[0];
    const int*   ei    = (const int*)d_in[1];
    const int*   batch = (const int*)d_in[2];
    const float* attW[3]  = {(const float*)d_in[3],  (const float*)d_in[9],  (const float*)d_in[15]};
    const float* asrc[3]  = {(const float*)d_in[4],  (const float*)d_in[10], (const float*)d_in[16]};
    const float* adst[3]  = {(const float*)d_in[5],  (const float*)d_in[11], (const float*)d_in[17]};
    const float* attb[3]  = {(const float*)d_in[6],  (const float*)d_in[12], (const float*)d_in[18]};
    const float* linW[3]  = {(const float*)d_in[7],  (const float*)d_in[13], (const float*)d_in[19]};
    const float* linb[3]  = {(const float*)d_in[8],  (const float*)d_in[14], (const float*)d_in[20]};
    const float* line1W = (const float*)d_in[21];
    const float* line1b = (const float*)d_in[22];
    const float* line2W = (const float*)d_in[23];
    const float* line2b = (const float*)d_in[24];
    float* out = (float*)d_out;

    static float* fbuf = nullptr;
    static int*   ibuf = nullptr;
    if (!fbuf) {
        cudaGetSymbolAddress((void**)&fbuf, g_fbuf);
        cudaGetSymbolAddress((void**)&ibuf, g_ibuf);
    }

    float* bh    = fbuf + OFF_H;
    float* bgat  = fbuf + OFF_GAT;
    float* bx    = fbuf + OFF_X;
    float* bals  = fbuf + OFF_ALS;
    float* bald  = fbuf + OFF_ALD;
    float* bpool = fbuf + OFF_POOL;
    float* bdense= fbuf + OFF_DENSE;
    int* deg    = ibuf + IOFF_DEG;
    int* rows   = ibuf + IOFF_ROWS;
    int* wp     = ibuf + IOFF_WP;
    int* csr    = ibuf + IOFF_CSR;
    int* gstart = ibuf + IOFF_GSTART;

    // ---- graph preprocessing (every call; deterministic work) ----
    {
        int n = GG * 512;  // >= NN
        k_init<<<(n + 255) / 256, 256>>>(deg, bpool);
        k_count<<<(EE + 255) / 256, 256>>>(ei, deg);
        k_scan<<<1, SCAN_T>>>(deg, rows, wp);
        k_scatter<<<(EE + NN + 255) / 256, 256>>>(ei, wp, csr);
        k_gstart<<<(NN + 255) / 256, 256>>>(batch, gstart);
    }

    // ---- three GAT layers ----
    const float* xcur = x_in;
    int fin = F_IN;
    for (int i = 0; i < 3; i++) {
        // h = x @ W   [N,fin] x [fin,512]
        {
            dim3 grid(HC / BN, (NN + BM - 1) / BM);
            k_sgemm<<<grid, 256>>>(xcur, attW[i], nullptr, bh, NN, fin, HC, 0);
        }
        // per-node attention terms
        k_al<<<(NN * 32 + 255) / 256, 256>>>(bh, asrc[i], adst[i], bals, bald);
        // softmax-attention aggregation (+ bias + relu)
        k_attn<<<(NN * 32 + 255) / 256, 256>>>(bh, bals, bald, attb[i], rows, csr, bgat);
        // x = relu(gat @ lin_W + lin_b)   [N,512] x [512,256]
        {
            dim3 grid(EMB / BN, (NN + BM - 1) / BM);
            k_sgemm<<<grid, 256>>>(bgat, linW[i], linb[i], bx, NN, HC, EMB, 1);
        }
        // pooling accumulation
        k_pool<<<GG, 256>>>(bx, gstart, bpool);
        xcur = bx;
        fin = EMB;
    }

    // ---- MLP head ----
    {
        dim3 grid(DENSE / BN, (GG + BM - 1) / BM);
        k_sgemm<<<grid, 256>>>(bpool, line1W, line1b, bdense, GG, 2 * EMB, DENSE, 1);
    }
    k_line2<<<GG, 512>>>(bdense, line2W, line2b, out);
}

// round 6
// speedup vs baseline: 4.2401x; 2.2024x over previous
#include <cuda_runtime.h>
#include <cuda_bf16.h>
#include <cstddef>
#include <cstdint>

// ---------------- problem constants ----------------
#define NN 20000
#define EE 240000
#define GG 128
#define F_IN 128
#define EMB 256
#define HH 2
#define HC 512          // H*EMB
#define DENSE 512
#define NCLS 10

// ---------------- scratch (device globals; no allocation) ----------------
#define OFF_H     0                         // [N,512]
#define OFF_GAT   (OFF_H   + NN*512)        // [N,512]
#define OFF_X     (OFF_GAT + NN*512)        // [N,256]
#define OFF_ALS   (OFF_X   + NN*256)        // [N,2]
#define OFF_ALD   (OFF_ALS + NN*2)          // [N,2]
#define OFF_POOL  (OFF_ALD + NN*2)          // [G,512] accumulated reps
#define OFF_DENSE (OFF_POOL + GG*512)       // [G,512]
#define FBUF_SZ   (OFF_DENSE + GG*512)

__device__ float g_fbuf[FBUF_SZ];

#define IOFF_DEG    0
#define IOFF_ROWS   (IOFF_DEG + NN)         // N+1
#define IOFF_WP     (IOFF_ROWS + NN + 1)    // N+1
#define IOFF_CSR    (IOFF_WP + NN + 1)      // E+N
#define IOFF_GSTART (IOFF_CSR + EE + NN)    // G+1
#define IBUF_SZ     (IOFF_GSTART + GG + 1)

__device__ int g_ibuf[IBUF_SZ];

// ---------------- init: deg=1 (self loop), zero pooled accumulator ----------------
__global__ void k_init(int* deg, float* pool) {
    int i = blockIdx.x * blockDim.x + threadIdx.x;
    if (i < NN) deg[i] = 1;
    if (i < GG * 512) pool[i] = 0.f;
}

// count in-degrees of real edges
__global__ void k_count(const int* __restrict__ ei, int* deg) {
    int e = blockIdx.x * blockDim.x + threadIdx.x;
    if (e < EE) atomicAdd(&deg[ei[EE + e]], 1);
}

// exclusive scan of deg[0..N) -> rows[0..N] AND wp[0..N], single block of 1024
#define SCAN_T 1024
__global__ void k_scan(const int* __restrict__ deg, int* rows, int* wp) {
    __shared__ int sh[SCAN_T];
    int tid = threadIdx.x;
    const int items = (NN + SCAN_T - 1) / SCAN_T;
    int start = tid * items;
    int local = 0;
    for (int i = 0; i < items; i++) {
        int idx = start + i;
        if (idx < NN) local += deg[idx];
    }
    sh[tid] = local;
    __syncthreads();
    for (int d = 1; d < SCAN_T; d <<= 1) {
        int v = (tid >= d) ? sh[tid - d] : 0;
        __syncthreads();
        sh[tid] += v;
        __syncthreads();
    }
    int run = sh[tid] - local;  // exclusive offset
    for (int i = 0; i < items; i++) {
        int idx = start + i;
        if (idx < NN) { rows[idx] = run; wp[idx] = run; run += deg[idx]; }
    }
    if (tid == SCAN_T - 1) { rows[NN] = sh[SCAN_T - 1]; wp[NN] = sh[SCAN_T - 1]; }
}

// scatter edges (and self loops) into CSR-by-dst
__global__ void k_scatter(const int* __restrict__ ei, int* wp, int* csr) {
    int i = blockIdx.x * blockDim.x + threadIdx.x;
    if (i >= EE + NN) return;
    int s, d;
    if (i < EE) { s = ei[i]; d = ei[EE + i]; }
    else        { s = d = i - EE; }
    int pos = atomicAdd(&wp[d], 1);
    csr[pos] = s;
}

// graph boundaries from sorted batch_index
__global__ void k_gstart(const int* __restrict__ batch, int* gstart) {
    int v = blockIdx.x * blockDim.x + threadIdx.x;
    if (v >= NN) return;
    int b = batch[v];
    if (v == 0) {
        for (int g = 0; g <= b; g++) gstart[g] = 0;
    } else {
        int bp = batch[v - 1];
        for (int g = bp + 1; g <= b; g++) gstart[g] = v;
    }
    if (v == NN - 1) {
        for (int g = b + 1; g <= GG; g++) gstart[g] = NN;
    }
}

// ---------------- tf32 tensor-core GEMM -----------------------------------
// C[M,Nc] = A[M,K] * B[K,Nc] (+bias)(+relu), fp32 accumulate.
// CTA tile 128x128x32; 8 warps (2M x 4N), warp tile 64x32 = 4x4 m16n8k8.
// A/B converted to tf32 (cvt.rna) at smem-store time.
// Smem pads: As row stride 36, Bs row stride 132 -> conflict-free LDS.

__device__ __forceinline__ uint32_t f2tf32(float f) {
    uint32_t r;
    asm("cvt.rna.tf32.f32 %0, %1;" : "=r"(r) : "f"(f));
    return r;
}

#define MMA_TF32(c, a, b) \
    asm("mma.sync.aligned.m16n8k8.row.col.f32.tf32.tf32.f32 " \
        "{%0,%1,%2,%3}, {%4,%5,%6,%7}, {%8,%9}, {%0,%1,%2,%3};" \
        : "+f"((c)[0]), "+f"((c)[1]), "+f"((c)[2]), "+f"((c)[3]) \
        : "r"((a)[0]), "r"((a)[1]), "r"((a)[2]), "r"((a)[3]), \
          "r"((b)[0]), "r"((b)[1]))

#define AS_STRIDE 36
#define BS_STRIDE 132

__global__ __launch_bounds__(256, 2) void k_mma(
    const float* __restrict__ A, const float* __restrict__ B,
    const float* __restrict__ bias, float* __restrict__ C,
    int M, int K, int Nc, int doRelu)
{
    __shared__ uint32_t AsU[128 * AS_STRIDE];   // 18 KB
    __shared__ uint32_t BsU[32 * BS_STRIDE];    // 16.5 KB
    int tid = threadIdx.x;
    int wid = tid >> 5, lane = tid & 31;
    int wm = (wid >> 2) * 64;       // 0 or 64
    int wn = (wid & 3) * 32;        // 0,32,64,96
    int gid = lane >> 2, tig = lane & 3;
    int rowBase = blockIdx.y * 128;
    int colBase = blockIdx.x * 128;

    float c[4][4][4];
#pragma unroll
    for (int mt = 0; mt < 4; mt++)
#pragma unroll
        for (int nt = 0; nt < 4; nt++)
#pragma unroll
            for (int r = 0; r < 4; r++) c[mt][nt][r] = 0.f;

    for (int k0 = 0; k0 < K; k0 += 32) {
        // ---- A tile: 128 rows x 32 cols ----
#pragma unroll
        for (int i = 0; i < 4; i++) {
            int idx = tid + i * 256;            // 0..1023
            int r = idx >> 3, c4 = (idx & 7) * 4;
            int gr = rowBase + r;
            float4 v;
            if (gr < M) v = *(const float4*)(A + (size_t)gr * K + k0 + c4);
            else        v = make_float4(0.f, 0.f, 0.f, 0.f);
            uint32_t* dst = &AsU[r * AS_STRIDE + c4];
            dst[0] = f2tf32(v.x); dst[1] = f2tf32(v.y);
            dst[2] = f2tf32(v.z); dst[3] = f2tf32(v.w);
        }
        // ---- B tile: 32 rows x 128 cols ----
#pragma unroll
        for (int i = 0; i < 4; i++) {
            int idx = tid + i * 256;
            int r = idx >> 5, c4 = (idx & 31) * 4;
            float4 v = *(const float4*)(B + (size_t)(k0 + r) * Nc + colBase + c4);
            uint32_t* dst = &BsU[r * BS_STRIDE + c4];
            dst[0] = f2tf32(v.x); dst[1] = f2tf32(v.y);
            dst[2] = f2tf32(v.z); dst[3] = f2tf32(v.w);
        }
        __syncthreads();

#pragma unroll
        for (int ks = 0; ks < 4; ks++) {
            uint32_t a[4][4], b[4][2];
#pragma unroll
            for (int mt = 0; mt < 4; mt++) {
                int r0 = wm + mt * 16 + gid;
                a[mt][0] = AsU[(r0)     * AS_STRIDE + ks * 8 + tig];
                a[mt][1] = AsU[(r0 + 8) * AS_STRIDE + ks * 8 + tig];
                a[mt][2] = AsU[(r0)     * AS_STRIDE + ks * 8 + tig + 4];
                a[mt][3] = AsU[(r0 + 8) * AS_STRIDE + ks * 8 + tig + 4];
            }
#pragma unroll
            for (int nt = 0; nt < 4; nt++) {
                int cc = wn + nt * 8 + gid;
                b[nt][0] = BsU[(ks * 8 + tig)     * BS_STRIDE + cc];
                b[nt][1] = BsU[(ks * 8 + tig + 4) * BS_STRIDE + cc];
            }
#pragma unroll
            for (int mt = 0; mt < 4; mt++)
#pragma unroll
                for (int nt = 0; nt < 4; nt++)
                    MMA_TF32(c[mt][nt], a[mt], b[nt]);
        }
        __syncthreads();
    }

    // ---- epilogue ----
#pragma unroll
    for (int mt = 0; mt < 4; mt++) {
        int r0 = rowBase + wm + mt * 16 + gid;
        int r1 = r0 + 8;
#pragma unroll
        for (int nt = 0; nt < 4; nt++) {
            int cc = colBase + wn + nt * 8 + 2 * tig;
            float2 v0 = make_float2(c[mt][nt][0], c[mt][nt][1]);
            float2 v1 = make_float2(c[mt][nt][2], c[mt][nt][3]);
            if (bias) {
                float b0 = bias[cc], b1 = bias[cc + 1];
                v0.x += b0; v0.y += b1; v1.x += b0; v1.y += b1;
            }
            if (doRelu) {
                v0.x = fmaxf(v0.x, 0.f); v0.y = fmaxf(v0.y, 0.f);
                v1.x = fmaxf(v1.x, 0.f); v1.y = fmaxf(v1.y, 0.f);
            }
            if (r0 < M) *(float2*)(C + (size_t)r0 * Nc + cc) = v0;
            if (r1 < M) *(float2*)(C + (size_t)r1 * Nc + cc) = v1;
        }
    }
}

// ---------------- per-node attention logit terms ----------------
__global__ void k_al(const float* __restrict__ h, const float* __restrict__ asrc,
                     const float* __restrict__ adst, float* __restrict__ als,
                     float* __restrict__ ald)
{
    int warp = (blockIdx.x * blockDim.x + threadIdx.x) >> 5;
    int lane = threadIdx.x & 31;
    if (warp >= NN) return;
    const float* hr = h + (size_t)warp * 512;
    float s0 = 0.f, s1 = 0.f, d0 = 0.f, d1 = 0.f;
#pragma unroll
    for (int i = 0; i < 8; i++) {
        int c = i * 32 + lane;
        float h0 = hr[c], h1 = hr[256 + c];
        s0 += h0 * asrc[c];        d0 += h0 * adst[c];
        s1 += h1 * asrc[256 + c];  d1 += h1 * adst[256 + c];
    }
#pragma unroll
    for (int off = 16; off; off >>= 1) {
        s0 += __shfl_xor_sync(0xffffffffu, s0, off);
        s1 += __shfl_xor_sync(0xffffffffu, s1, off);
        d0 += __shfl_xor_sync(0xffffffffu, d0, off);
        d1 += __shfl_xor_sync(0xffffffffu, d1, off);
    }
    if (lane == 0) {
        als[warp * 2] = s0; als[warp * 2 + 1] = s1;
        ald[warp * 2] = d0; ald[warp * 2 + 1] = d1;
    }
}

// ---------------- attention softmax + aggregation (one warp per dst node) -----------
__global__ void k_attn(const float* __restrict__ h, const float* __restrict__ als,
                       const float* __restrict__ ald, const float* __restrict__ bvec,
                       const int* __restrict__ rows, const int* __restrict__ csr,
                       float* __restrict__ out)
{
    int warp = (blockIdx.x * blockDim.x + threadIdx.x) >> 5;
    int lane = threadIdx.x & 31;
    if (warp >= NN) return;
    int v = warp;
    int s0 = rows[v], s1 = rows[v + 1];
    int deg = s1 - s0;
    float ad0 = ald[v * 2], ad1 = ald[v * 2 + 1];

    // pass 1: max logit per head
    float m0 = -1e30f, m1 = -1e30f;
    for (int base = 0; base < deg; base += 32) {
        int j = base + lane;
        if (j < deg) {
            int s = csr[s0 + j];
            float t0 = als[s * 2] + ad0;     t0 = fmaxf(t0, 0.2f * t0);
            float t1 = als[s * 2 + 1] + ad1; t1 = fmaxf(t1, 0.2f * t1);
            m0 = fmaxf(m0, t0); m1 = fmaxf(m1, t1);
        }
    }
#pragma unroll
    for (int off = 16; off; off >>= 1) {
        m0 = fmaxf(m0, __shfl_xor_sync(0xffffffffu, m0, off));
        m1 = fmaxf(m1, __shfl_xor_sync(0xffffffffu, m1, off));
    }

    // pass 2: exp weights + weighted aggregation, 2 edges/iter for load MLP
    float acc[16];
#pragma unroll
    for (int k = 0; k < 16; k++) acc[k] = 0.f;
    float den0 = 0.f, den1 = 0.f;
    int j = 0;
    for (; j + 2 <= deg; j += 2) {
        int sa = csr[s0 + j];
        int sb = csr[s0 + j + 1];
        float ta0 = als[sa * 2] + ad0;     ta0 = fmaxf(ta0, 0.2f * ta0);
        float ta1 = als[sa * 2 + 1] + ad1; ta1 = fmaxf(ta1, 0.2f * ta1);
        float tb0 = als[sb * 2] + ad0;     tb0 = fmaxf(tb0, 0.2f * tb0);
        float tb1 = als[sb * 2 + 1] + ad1; tb1 = fmaxf(tb1, 0.2f * tb1);
        float wa0 = __expf(ta0 - m0), wa1 = __expf(ta1 - m1);
        float wb0 = __expf(tb0 - m0), wb1 = __expf(tb1 - m1);
        den0 += wa0 + wb0; den1 += wa1 + wb1;
        const float* ha = h + (size_t)sa * 512 + lane;
        const float* hb = h + (size_t)sb * 512 + lane;
#pragma unroll
        for (int k = 0; k < 16; k++) {
            float va = ha[k * 32];
            float vb = hb[k * 32];
            acc[k] += (k < 8 ? wa0 : wa1) * va + (k < 8 ? wb0 : wb1) * vb;
        }
    }
    for (; j < deg; j++) {
        int s = csr[s0 + j];
        float t0 = als[s * 2] + ad0;     t0 = fmaxf(t0, 0.2f * t0);
        float t1 = als[s * 2 + 1] + ad1; t1 = fmaxf(t1, 0.2f * t1);
        float w0 = __expf(t0 - m0), w1 = __expf(t1 - m1);
        den0 += w0; den1 += w1;
        const float* hr = h + (size_t)s * 512 + lane;
#pragma unroll
        for (int k = 0; k < 16; k++)
            acc[k] += (k < 8 ? w0 : w1) * hr[k * 32];
    }
    float r0 = 1.0f / den0, r1 = 1.0f / den1;
    float* orow = out + (size_t)v * 512 + lane;
#pragma unroll
    for (int k = 0; k < 16; k++) {
        float val = acc[k] * (k < 8 ? r0 : r1) + bvec[k * 32 + lane];
        orow[k * 32] = fmaxf(val, 0.f);   // fused relu (post-GAT)
    }
}

// ---------------- pooling: per-graph max + mean, accumulated across layers ----------
__global__ void k_pool(const float* __restrict__ x, const int* __restrict__ gstart,
                       float* __restrict__ gacc)
{
    int g = blockIdx.x;
    int c = threadIdx.x;   // 256
    int s = gstart[g], e = gstart[g + 1];
    float mx = 0.f, sm = 0.f;   // post-relu values are >= 0
    int v = s;
    for (; v + 2 <= e; v += 2) {
        float a = x[(size_t)v * 256 + c];
        float b = x[(size_t)(v + 1) * 256 + c];
        sm += a + b; mx = fmaxf(mx, fmaxf(a, b));
    }
    if (v < e) {
        float a = x[(size_t)v * 256 + c];
        sm += a; mx = fmaxf(mx, a);
    }
    int cnt = e - s;
    float mean = (cnt > 0) ? sm / (float)cnt : 0.f;
    gacc[g * 512 + c]       += mx;
    gacc[g * 512 + 256 + c] += mean;
}

// ---------------- final tiny linear: [G,512] @ [512,10] + b ----------------
__global__ void k_line2(const float* __restrict__ gd, const float* __restrict__ W,
                        const float* __restrict__ b, float* __restrict__ out)
{
    __shared__ float sh[512];
    int g = blockIdx.x;
    for (int i = threadIdx.x; i < 512; i += blockDim.x) sh[i] = gd[g * 512 + i];
    __syncthreads();
    if (threadIdx.x < NCLS) {
        float acc = b[threadIdx.x];
        for (int k = 0; k < 512; k++) acc += sh[k] * W[k * NCLS + threadIdx.x];
        out[g * NCLS + threadIdx.x] = acc;
    }
}

// ---------------- host orchestration ----------------
extern "C" void kernel_launch(void* const* d_in, const int* in_sizes, int n_in,
                              void* d_out, int out_size)
{
    const float* x_in  = (const float*)d_in[0];
    const int*   ei    = (const int*)d_in[1];
    const int*   batch = (const int*)d_in[2];
    const float* attW[3]  = {(const float*)d_in[3],  (const float*)d_in[9],  (const float*)d_in[15]};
    const float* asrc[3]  = {(const float*)d_in[4],  (const float*)d_in[10], (const float*)d_in[16]};
    const float* adst[3]  = {(const float*)d_in[5],  (const float*)d_in[11], (const float*)d_in[17]};
    const float* attb[3]  = {(const float*)d_in[6],  (const float*)d_in[12], (const float*)d_in[18]};
    const float* linW[3]  = {(const float*)d_in[7],  (const float*)d_in[13], (const float*)d_in[19]};
    const float* linb[3]  = {(const float*)d_in[8],  (const float*)d_in[14], (const float*)d_in[20]};
    const float* line1W = (const float*)d_in[21];
    const float* line1b = (const float*)d_in[22];
    const float* line2W = (const float*)d_in[23];
    const float* line2b = (const float*)d_in[24];
    float* out = (float*)d_out;

    static float* fbuf = nullptr;
    static int*   ibuf = nullptr;
    if (!fbuf) {
        cudaGetSymbolAddress((void**)&fbuf, g_fbuf);
        cudaGetSymbolAddress((void**)&ibuf, g_ibuf);
    }

    float* bh    = fbuf + OFF_H;
    float* bgat  = fbuf + OFF_GAT;
    float* bx    = fbuf + OFF_X;
    float* bals  = fbuf + OFF_ALS;
    float* bald  = fbuf + OFF_ALD;
    float* bpool = fbuf + OFF_POOL;
    float* bdense= fbuf + OFF_DENSE;
    int* deg    = ibuf + IOFF_DEG;
    int* rows   = ibuf + IOFF_ROWS;
    int* wp     = ibuf + IOFF_WP;
    int* csr    = ibuf + IOFF_CSR;
    int* gstart = ibuf + IOFF_GSTART;

    // ---- graph preprocessing (every call; deterministic work) ----
    {
        int n = GG * 512;  // >= NN
        k_init<<<(n + 255) / 256, 256>>>(deg, bpool);
        k_count<<<(EE + 255) / 256, 256>>>(ei, deg);
        k_scan<<<1, SCAN_T>>>(deg, rows, wp);
        k_scatter<<<(EE + NN + 255) / 256, 256>>>(ei, wp, csr);
        k_gstart<<<(NN + 255) / 256, 256>>>(batch, gstart);
    }

    // ---- three GAT layers ----
    const float* xcur = x_in;
    int fin = F_IN;
    int mtiles = (NN + 127) / 128;
    for (int i = 0; i < 3; i++) {
        // h = x @ W   [N,fin] x [fin,512]
        {
            dim3 grid(HC / 128, mtiles);
            k_mma<<<grid, 256>>>(xcur, attW[i], nullptr, bh, NN, fin, HC, 0);
        }
        // per-node attention terms
        k_al<<<(NN * 32 + 255) / 256, 256>>>(bh, asrc[i], adst[i], bals, bald);
        // softmax-attention aggregation (+ bias + relu)
        k_attn<<<(NN * 32 + 255) / 256, 256>>>(bh, bals, bald, attb[i], rows, csr, bgat);
        // x = relu(gat @ lin_W + lin_b)   [N,512] x [512,256]
        {
            dim3 grid(EMB / 128, mtiles);
            k_mma<<<grid, 256>>>(bgat, linW[i], linb[i], bx, NN, HC, EMB, 1);
        }
        // pooling accumulation
        k_pool<<<GG, 256>>>(bx, gstart, bpool);
        xcur = bx;
        fin = EMB;
    }

    // ---- MLP head ----
    {
        dim3 grid(DENSE / 128, 1);
        k_mma<<<grid, 256>>>(bpool, line1W, line1b, bdense, GG, 2 * EMB, DENSE, 1);
    }
    k_line2<<<GG, 512>>>(bdense, line2W, line2b, out);
}